// round 3
// baseline (speedup 1.0000x reference)
#include <cuda_runtime.h>
#include <cstdint>

// WHTConv2D: y = FWHT2( soft_threshold(W @ (v * FWHT2(x)), T) + FWHT2(x) ) / (H*W)
// Shapes: x[32,64,128,128] f32, W[64,64], v[128,128], T[128,128]
// B=32, C=64, H=W=128, HW=16384, planes = B*C = 2048
//
// Identity: x = FWHT2(FWHT2(x))/(H*W) and FWHT2 linear =>
//   y = FWHT2( soft_threshold(W@(v*f2),T) + f2 ) / (H*W),  f2 = FWHT2(x)
// => never re-read x; 768 MB total DRAM traffic over 3 kernels.

#define HW      16384
#define NPLANES 2048
#define SM_PITCH 129   // 128 + 1 padding: conflict-free column access

// 128 MB scratch (static __device__ global: no runtime allocation)
__device__ float g_scratch[33554432];

__device__ __forceinline__ float bf_shfl(float v, int st, int lane) {
    float t = __shfl_xor_sync(0xffffffffu, v, st);
    return (lane & st) ? (t - v) : (v + t);
}

// Full 7-stage FWHT-128 on 4 registers laid out as element e = lane + 32*s.
__device__ __forceinline__ void fwht128_regs(float& v0, float& v1, float& v2, float& v3, int lane) {
    float a;
    a = v0 + v1; v1 = v0 - v1; v0 = a;   // stride 32
    a = v2 + v3; v3 = v2 - v3; v2 = a;
    a = v0 + v2; v2 = v0 - v2; v0 = a;   // stride 64
    a = v1 + v3; v3 = v1 - v3; v1 = a;
#pragma unroll
    for (int st = 16; st >= 1; st >>= 1) {   // strides 16..1 via shuffles
        v0 = bf_shfl(v0, st, lane);
        v1 = bf_shfl(v1, st, lane);
        v2 = bf_shfl(v2, st, lane);
        v3 = bf_shfl(v3, st, lane);
    }
}

// One CTA = one 128x128 plane: row FWHT (gmem->regs->smem), column FWHT
// (strided smem, padded pitch), coalesced write-back to g_scratch.
__global__ void __launch_bounds__(512)
fwht_plane_fwd_kernel(const float* __restrict__ in)
{
    extern __shared__ float sm[];
    const long base = (long)blockIdx.x * HW;
    const int t = threadIdx.x;
    const int lane = t & 31;
    const int warp = t >> 5;

#pragma unroll
    for (int i = 0; i < 8; i++) {
        const int r = (warp << 3) + i;
        const float* row = in + base + r * 128;
        float v0 = row[lane];
        float v1 = row[lane + 32];
        float v2 = row[lane + 64];
        float v3 = row[lane + 96];
        fwht128_regs(v0, v1, v2, v3, lane);
        float* srow = sm + r * SM_PITCH;
        srow[lane]      = v0;
        srow[lane + 32] = v1;
        srow[lane + 64] = v2;
        srow[lane + 96] = v3;
    }
    __syncthreads();

#pragma unroll
    for (int i = 0; i < 8; i++) {
        const int c = (warp << 3) + i;
        float v0 = sm[(lane)      * SM_PITCH + c];
        float v1 = sm[(lane + 32) * SM_PITCH + c];
        float v2 = sm[(lane + 64) * SM_PITCH + c];
        float v3 = sm[(lane + 96) * SM_PITCH + c];
        fwht128_regs(v0, v1, v2, v3, lane);
        sm[(lane)      * SM_PITCH + c] = v0;
        sm[(lane + 32) * SM_PITCH + c] = v1;
        sm[(lane + 64) * SM_PITCH + c] = v2;
        sm[(lane + 96) * SM_PITCH + c] = v3;
    }
    __syncthreads();

#pragma unroll
    for (int i = 0; i < 8; i++) {
        const int r = (warp << 3) + i;
        const float* srow = sm + r * SM_PITCH;
        float* orow = g_scratch + base + r * 128;
        orow[lane]      = srow[lane];
        orow[lane + 32] = srow[lane + 32];
        orow[lane + 64] = srow[lane + 64];
        orow[lane + 96] = srow[lane + 96];
    }
}

__global__ void __launch_bounds__(512)
fwht_plane_final_kernel(float* __restrict__ out)
{
    extern __shared__ float sm[];
    const long base = (long)blockIdx.x * HW;
    const int t = threadIdx.x;
    const int lane = t & 31;
    const int warp = t >> 5;
    const float scale = 1.0f / 16384.0f;

#pragma unroll
    for (int i = 0; i < 8; i++) {
        const int r = (warp << 3) + i;
        const float* row = g_scratch + base + r * 128;
        float v0 = row[lane];
        float v1 = row[lane + 32];
        float v2 = row[lane + 64];
        float v3 = row[lane + 96];
        fwht128_regs(v0, v1, v2, v3, lane);
        float* srow = sm + r * SM_PITCH;
        srow[lane]      = v0;
        srow[lane + 32] = v1;
        srow[lane + 64] = v2;
        srow[lane + 96] = v3;
    }
    __syncthreads();

#pragma unroll
    for (int i = 0; i < 8; i++) {
        const int c = (warp << 3) + i;
        float v0 = sm[(lane)      * SM_PITCH + c];
        float v1 = sm[(lane + 32) * SM_PITCH + c];
        float v2 = sm[(lane + 64) * SM_PITCH + c];
        float v3 = sm[(lane + 96) * SM_PITCH + c];
        fwht128_regs(v0, v1, v2, v3, lane);
        sm[(lane)      * SM_PITCH + c] = v0;
        sm[(lane + 32) * SM_PITCH + c] = v1;
        sm[(lane + 64) * SM_PITCH + c] = v2;
        sm[(lane + 96) * SM_PITCH + c] = v3;
    }
    __syncthreads();

#pragma unroll
    for (int i = 0; i < 8; i++) {
        const int r = (warp << 3) + i;
        const float* srow = sm + r * SM_PITCH;
        float* orow = out + base + r * 128;
        orow[lane]      = srow[lane]      * scale;
        orow[lane + 32] = srow[lane + 32] * scale;
        orow[lane + 64] = srow[lane + 64] * scale;
        orow[lane + 96] = srow[lane + 96] * scale;
    }
}

// Channel mix + soft-threshold + residual, in-place on g_scratch.
// Grid: (HW/256 tiles, B). CTA: 256 threads, tile = all 64 channels x 256 pixels.
// out[o,p] = soft_threshold(v[p] * sum_c W[o,c]*f2[c,p], T[p]) + f2[o,p]
// In-place safe: CTA stages its whole (64ch x 256px) tile in smem before writing.
__global__ void __launch_bounds__(256, 2)
mix_kernel(const float* __restrict__ Wm,
           const float* __restrict__ vmap, const float* __restrict__ Tmap)
{
    extern __shared__ float smbuf[];
    float* Wt = smbuf;           // [c][o]  64*64
    float* Xs = smbuf + 4096;    // [c][p]  64*256
    const int t = threadIdx.x;
    const int b = blockIdx.y;
    const int pbase = blockIdx.x << 8;   // 256-pixel tile within plane

    // Load W transposed: Wt[c][o] = W[o][c]
#pragma unroll
    for (int i = 0; i < 16; i++) {
        int idx = t + (i << 8);
        int o = idx >> 6, c = idx & 63;
        Wt[(c << 6) + o] = __ldg(Wm + idx);
    }
    // Load X tile: Xs[c][p] = f2[b,c,pbase+p]  (float4 coalesced)
#pragma unroll
    for (int i = 0; i < 16; i++) {
        int f4i = t + (i << 8);
        int c = f4i >> 6, col = f4i & 63;
        reinterpret_cast<float4*>(Xs)[(c << 6) + col] =
            *reinterpret_cast<const float4*>(g_scratch + (long)(b * 64 + c) * HW + pbase + (col << 2));
    }
    __syncthreads();

    const int to = (t & 7) << 3;   // output-channel offset (8 rows)
    const int tp = (t >> 3) << 3;  // pixel offset (8 cols)

    float acc[8][8];
#pragma unroll
    for (int o = 0; o < 8; o++)
#pragma unroll
        for (int p = 0; p < 8; p++) acc[o][p] = 0.0f;

#pragma unroll 8
    for (int c = 0; c < 64; c++) {
        float af[8], bfv[8];
        *reinterpret_cast<float4*>(af)      = *reinterpret_cast<const float4*>(&Wt[(c << 6) + to]);
        *reinterpret_cast<float4*>(af + 4)  = *reinterpret_cast<const float4*>(&Wt[(c << 6) + to + 4]);
        *reinterpret_cast<float4*>(bfv)     = *reinterpret_cast<const float4*>(&Xs[(c << 8) + tp]);
        *reinterpret_cast<float4*>(bfv + 4) = *reinterpret_cast<const float4*>(&Xs[(c << 8) + tp + 4]);
#pragma unroll
        for (int o = 0; o < 8; o++)
#pragma unroll
            for (int p = 0; p < 8; p++)
                acc[o][p] = fmaf(af[o], bfv[p], acc[o][p]);
    }

    // Epilogue: v-scale, soft-threshold (sign via bit ops), residual, store
    float vv[8], tt[8];
#pragma unroll
    for (int p = 0; p < 8; p++) {
        vv[p] = __ldg(vmap + pbase + tp + p);
        tt[p] = fmaxf(__ldg(Tmap + pbase + tp + p), 0.0f);   // relu(T)
    }
#pragma unroll
    for (int o = 0; o < 8; o++) {
        const int og = to + o;
        float outv[8];
#pragma unroll
        for (int p = 0; p < 8; p++) {
            float z = vv[p] * acc[o][p];
            float m = fmaxf(fabsf(z) - tt[p], 0.0f);
            uint32_t sgn = __float_as_uint(z) & 0x80000000u;
            float st = __uint_as_float(__float_as_uint(m) | sgn);
            outv[p] = st + Xs[(og << 8) + tp + p];  // + f2 residual
        }
        float* dst = g_scratch + (long)(b * 64 + og) * HW + pbase + tp;
        *reinterpret_cast<float4*>(dst)     = *reinterpret_cast<float4*>(outv);
        *reinterpret_cast<float4*>(dst + 4) = *reinterpret_cast<float4*>(outv + 4);
    }
}

extern "C" void kernel_launch(void* const* d_in, const int* in_sizes, int n_in,
                              void* d_out, int out_size)
{
    (void)in_sizes; (void)n_in; (void)out_size;
    const float* x  = (const float*)d_in[0];
    const float* Wm = (const float*)d_in[1];
    const float* v  = (const float*)d_in[2];
    const float* T  = (const float*)d_in[3];
    float* y = (float*)d_out;

    const int fwht_smem = 128 * SM_PITCH * sizeof(float);    // 66048 B
    const int mix_smem  = (4096 + 64 * 256) * sizeof(float); // 81920 B
    cudaFuncSetAttribute(fwht_plane_fwd_kernel,   cudaFuncAttributeMaxDynamicSharedMemorySize, fwht_smem);
    cudaFuncSetAttribute(fwht_plane_final_kernel, cudaFuncAttributeMaxDynamicSharedMemorySize, fwht_smem);
    cudaFuncSetAttribute(mix_kernel,              cudaFuncAttributeMaxDynamicSharedMemorySize, mix_smem);

    // K1: g_scratch = FWHT2(x)
    fwht_plane_fwd_kernel<<<NPLANES, 512, fwht_smem>>>(x);
    // K2: g_scratch = soft_threshold(W @ (v*f2), T) + f2   (in-place)
    mix_kernel<<<dim3(HW / 256, 32), 256, mix_smem>>>(Wm, v, T);
    // K3: y = FWHT2(g_scratch) / (H*W)
    fwht_plane_final_kernel<<<NPLANES, 512, fwht_smem>>>(y);
}

// round 4
// speedup vs baseline: 1.2905x; 1.2905x over previous
#include <cuda_runtime.h>
#include <cstdint>

// WHTConv2D: y = FWHT2( soft_threshold(W @ (v * FWHT2(x)), T) + FWHT2(x) ) / (H*W)
// x[32,64,128,128] f32, W[64,64], v[128,128], T[128,128]
// Identity: y = FWHT2( soft_threshold(W@(v*f2),T) + f2 ) / 16384,  f2 = FWHT2(x)
//
// FWHT2 of a 128x128 plane == 14-bit Hadamard on the flattened index e[13:0]
// (rows = e[13:7], cols = e[6:0]; all bit-butterflies commute). We cover the
// 14 bits in 3 register rounds (bits 13..9, 8..4, 3..0) with XOR-swizzled
// smem exchanges in between -> ZERO shuffles (R3 ncu showed SHFL-driven
// l1tex = 75% was the binding constraint).

#define HW      16384
#define NPLANES 2048

// 128 MB scratch (static __device__ global: no runtime allocation)
__device__ float g_scratch[33554432];

// 5-stage in-register FWHT over reg-index bits [4:0] (32 regs).
__device__ __forceinline__ void fwht_regs32(float* d) {
#pragma unroll
    for (int s = 1; s <= 16; s <<= 1) {
#pragma unroll
        for (int r = 0; r < 32; r++) {
            if (!(r & s)) {
                int q = r | s;
                float a = d[r] + d[q];
                d[q] = d[r] - d[q];
                d[r] = a;
            }
        }
    }
}
// 4-stage in-register FWHT over reg-index bits [3:0] (bit4 untouched).
__device__ __forceinline__ void fwht_regs16x2(float* d) {
#pragma unroll
    for (int s = 1; s <= 8; s <<= 1) {
#pragma unroll
        for (int r = 0; r < 32; r++) {
            if (!(r & s)) {
                int q = r | s;
                float a = d[r] + d[q];
                d[q] = d[r] - d[q];
                d[r] = a;
            }
        }
    }
}

// One CTA = one plane. 512 threads x 32 regs = 16384 elements.
// Round A: bits 13..9 (regs), X1, Round B: bits 8..4 (regs), X2,
// Round C: bits 3..0 (regs), X3 (output staging), coalesced STG.
// Swizzles (verified conflict-free for every store/load lane pattern):
//   a1(e) = e ^ (e9<<4);  a2(e) = e ^ e85 ^ (e9<<4);  a3(e) = e ^ e85
// where e9 = bit9 of e, e85 = (e>>5)&15.
__global__ void __launch_bounds__(512)
fwht2_kernel(const float* __restrict__ in, float* __restrict__ out, float scale)
{
    extern __shared__ float sm[];   // 16384 floats = 64 KB
    const long base = (long)blockIdx.x * HW;
    const int t = threadIdx.x;

    float d[32];

    // ---- Load: e = r*512 + t (coalesced per r) ----
#pragma unroll
    for (int r = 0; r < 32; r++) d[r] = in[base + r * 512 + t];

    // ---- Round A: bits 13..9 (e[13:9] = r) ----
    fwht_regs32(d);

    // ---- X1 store: a1 = e ^ (e9<<4), e9 = r&1 ----
#pragma unroll
    for (int r = 0; r < 32; r++) sm[(r * 512 + t) ^ ((r & 1) << 4)] = d[r];
    __syncthreads();

    // ---- X1 read: e = hi*512 + r*16 + lo, hi=t>>4 (e[13:9]), lo=t&15 (e[3:0]) ----
    {
        const int hi = t >> 4;
        const int lo = t & 15;
        const int x1 = (hi & 1) << 4;           // e9<<4
        const int eb = hi * 512 + lo;
#pragma unroll
        for (int r = 0; r < 32; r++) d[r] = sm[(eb + r * 16) ^ x1];
    }
    __syncthreads();

    // ---- Round B: bits 8..4 (e[8:4] = r) ----
    fwht_regs32(d);

    // ---- X2 store: a2 = e ^ (r>>1) ^ (e9<<4) ----
    {
        const int hi = t >> 4;
        const int lo = t & 15;
        const int x1 = (hi & 1) << 4;
        const int eb = hi * 512 + lo;
#pragma unroll
        for (int r = 0; r < 32; r++) sm[((eb + r * 16) ^ (r >> 1)) ^ x1] = d[r];
    }
    __syncthreads();

    // ---- X2 read: e = (t>>5)<<10 | (r>>4)<<9 | (t&31)<<4 | (r&15) ----
    //      regs: r[3:0]=e[3:0], r[4]=e9. a2 = e ^ ((t&31)>>1) ^ ((r>>4)<<4)
    {
        const int hb = (t >> 5) << 10;
        const int mb = (t & 31) << 4;
        const int x2 = (t & 31) >> 1;           // e[8:5]
        const int eb = hb | mb;
#pragma unroll
        for (int r = 0; r < 32; r++)
            d[r] = sm[((eb | ((r >> 4) << 9) | (r & 15)) ^ x2) ^ ((r >> 4) << 4)];
    }
    __syncthreads();

    // ---- Round C: bits 3..0 (e[3:0] = r[3:0]); r[4]=e9 untouched ----
    fwht_regs16x2(d);

    // ---- X3 store: a3 = e ^ ((t&31)>>1) ----
    {
        const int hb = (t >> 5) << 10;
        const int mb = (t & 31) << 4;
        const int x2 = (t & 31) >> 1;
        const int eb = hb | mb;
#pragma unroll
        for (int r = 0; r < 32; r++)
            sm[(eb | ((r >> 4) << 9) | (r & 15)) ^ x2] = d[r];
    }
    __syncthreads();

    // ---- X3 read + coalesced scaled store: e = r*512 + t, a3 = e ^ ((t>>5)&15) ----
    {
        const int x3 = (t >> 5) & 15;           // e[8:5]
#pragma unroll
        for (int r = 0; r < 32; r++)
            out[base + r * 512 + t] = sm[(r * 512 + t) ^ x3] * scale;
    }
}

// Channel mix + soft-threshold + residual, in-place on g_scratch.
// Grid: (HW/256, B). CTA: 256 threads. Warp w -> 8 output chans (warp-uniform
// W loads = LDS broadcast, halves smem crossbar bytes); lane l -> 8 pixels.
// out[o,p] = soft_threshold(v[p] * sum_c W[o,c]*f2[c,p], T[p]) + f2[o,p]
__global__ void __launch_bounds__(256)
mix_kernel(const float* __restrict__ Wm,
           const float* __restrict__ vmap, const float* __restrict__ Tmap)
{
    extern __shared__ float smbuf[];
    float* Wt = smbuf;           // [c][o]  64*64
    float* Xs = smbuf + 4096;    // [c][p]  64*256
    const int t = threadIdx.x;
    const int b = blockIdx.y;
    const int pbase = blockIdx.x << 8;   // 256-pixel tile

    // Load W transposed: Wt[c][o] = W[o][c]
#pragma unroll
    for (int i = 0; i < 16; i++) {
        int idx = t + (i << 8);
        int o = idx >> 6, c = idx & 63;
        Wt[(c << 6) + o] = __ldg(Wm + idx);
    }
    // Load X tile: Xs[c][p] = f2[b,c,pbase+p]  (float4 coalesced)
#pragma unroll
    for (int i = 0; i < 16; i++) {
        int f4i = t + (i << 8);
        int c = f4i >> 6, col = f4i & 63;
        reinterpret_cast<float4*>(Xs)[(c << 6) + col] =
            *reinterpret_cast<const float4*>(g_scratch + (long)(b * 64 + c) * HW + pbase + (col << 2));
    }
    __syncthreads();

    const int to = (t >> 5) << 3;   // warp-uniform: 8 output channels
    const int tp = (t & 31) << 3;   // per-lane: 8 pixels

    float acc[8][8];
#pragma unroll
    for (int o = 0; o < 8; o++)
#pragma unroll
        for (int p = 0; p < 8; p++) acc[o][p] = 0.0f;

#pragma unroll 8
    for (int c = 0; c < 64; c++) {
        float af[8], bfv[8];
        *reinterpret_cast<float4*>(af)      = *reinterpret_cast<const float4*>(&Wt[(c << 6) + to]);       // broadcast
        *reinterpret_cast<float4*>(af + 4)  = *reinterpret_cast<const float4*>(&Wt[(c << 6) + to + 4]);   // broadcast
        *reinterpret_cast<float4*>(bfv)     = *reinterpret_cast<const float4*>(&Xs[(c << 8) + tp]);
        *reinterpret_cast<float4*>(bfv + 4) = *reinterpret_cast<const float4*>(&Xs[(c << 8) + tp + 4]);
#pragma unroll
        for (int o = 0; o < 8; o++)
#pragma unroll
            for (int p = 0; p < 8; p++)
                acc[o][p] = fmaf(af[o], bfv[p], acc[o][p]);
    }

    // Epilogue: v-scale, soft-threshold, residual, store
    float vv[8], tt[8];
#pragma unroll
    for (int p = 0; p < 8; p++) {
        vv[p] = __ldg(vmap + pbase + tp + p);
        tt[p] = fmaxf(__ldg(Tmap + pbase + tp + p), 0.0f);   // relu(T)
    }
#pragma unroll
    for (int o = 0; o < 8; o++) {
        const int og = to + o;
        float res[8];
        *reinterpret_cast<float4*>(res)     = *reinterpret_cast<const float4*>(&Xs[(og << 8) + tp]);
        *reinterpret_cast<float4*>(res + 4) = *reinterpret_cast<const float4*>(&Xs[(og << 8) + tp + 4]);
        float outv[8];
#pragma unroll
        for (int p = 0; p < 8; p++) {
            float z = vv[p] * acc[o][p];
            float m = fmaxf(fabsf(z) - tt[p], 0.0f);
            uint32_t sgn = __float_as_uint(z) & 0x80000000u;
            outv[p] = __uint_as_float(__float_as_uint(m) | sgn) + res[p];
        }
        float* dst = g_scratch + (long)(b * 64 + og) * HW + pbase + tp;
        *reinterpret_cast<float4*>(dst)     = *reinterpret_cast<float4*>(outv);
        *reinterpret_cast<float4*>(dst + 4) = *reinterpret_cast<float4*>(outv + 4);
    }
}

extern "C" void kernel_launch(void* const* d_in, const int* in_sizes, int n_in,
                              void* d_out, int out_size)
{
    (void)in_sizes; (void)n_in; (void)out_size;
    const float* x  = (const float*)d_in[0];
    const float* Wm = (const float*)d_in[1];
    const float* v  = (const float*)d_in[2];
    const float* T  = (const float*)d_in[3];
    float* y = (float*)d_out;

    float* scratch;
    cudaGetSymbolAddress((void**)&scratch, g_scratch);

    const int fwht_smem = HW * sizeof(float);                // 65536 B
    const int mix_smem  = (4096 + 64 * 256) * sizeof(float); // 81920 B
    cudaFuncSetAttribute(fwht2_kernel, cudaFuncAttributeMaxDynamicSharedMemorySize, fwht_smem);
    cudaFuncSetAttribute(mix_kernel,   cudaFuncAttributeMaxDynamicSharedMemorySize, mix_smem);

    // K1: g_scratch = FWHT2(x)
    fwht2_kernel<<<NPLANES, 512, fwht_smem>>>(x, scratch, 1.0f);
    // K2: g_scratch = soft_threshold(W @ (v*f2), T) + f2   (in-place)
    mix_kernel<<<dim3(HW / 256, 32), 256, mix_smem>>>(Wm, v, T);
    // K3: y = FWHT2(g_scratch) / (H*W)
    fwht2_kernel<<<NPLANES, 512, fwht_smem>>>(scratch, y, 1.0f / 16384.0f);
}